// round 2
// baseline (speedup 1.0000x reference)
#include <cuda_runtime.h>
#include <math.h>

#define NMAX   50000
#define EMAX   700000     // 650000 edges + 50000 self loops
#define FDIM   256
#define HEADS  4
#define CH     64
#define NEG_SLOPE 0.2f

// ---------------- scratch (device globals: no allocation allowed) ----------
__device__ int   g_src [EMAX];
__device__ int   g_dst [EMAX];
__device__ int   g_ssrc[EMAX];          // src ids sorted by dst segment
__device__ int   g_deg [NMAX];
__device__ int   g_off [NMAX + 1];
__device__ int   g_cur [NMAX];
__device__ float g_feat[NMAX * FDIM];   // h = X @ W  (per layer)
__device__ float g_act [NMAX * FDIM];   // layer activation output
__device__ float g_alsrc[NMAX * HEADS];
__device__ float g_aldst[NMAX * HEADS];
__device__ float g_h3  [NMAX];
__device__ int   g_is64;

// ---------------- helpers --------------------------------------------------
__device__ __forceinline__ float lrelu(float x) { return x > 0.f ? x : NEG_SLOPE * x; }
__device__ __forceinline__ float wsum(float v) {
    #pragma unroll
    for (int o = 16; o; o >>= 1) v += __shfl_xor_sync(0xffffffffu, v, o);
    return v;
}
__device__ __forceinline__ float wmax(float v) {
    #pragma unroll
    for (int o = 16; o; o >>= 1) v = fmaxf(v, __shfl_xor_sync(0xffffffffu, v, o));
    return v;
}

// ---------------- graph build ----------------------------------------------
// Detect whether edge_index buffer is int64 or (silently downcast) int32.
__global__ void k_detect(const long long* e, int E) {
    int bad = 0;
    int lim = E < 4096 ? E : 4096;
    for (int i = threadIdx.x; i < lim; i += blockDim.x) {
        unsigned long long v = (unsigned long long)e[i];
        if (v >= (1ULL << 31)) bad = 1;          // int32 pair seen as int64
    }
    bad = __syncthreads_or(bad);
    if (threadIdx.x == 0) g_is64 = bad ? 0 : 1;
}

__global__ void k_build_edges(const void* eptr, int E, int N) {
    int i = blockIdx.x * blockDim.x + threadIdx.x;
    if (i < E) {
        int s, d;
        if (g_is64) {
            const long long* p = (const long long*)eptr;
            s = (int)p[i]; d = (int)p[E + i];
        } else {
            const int* p = (const int*)eptr;
            s = p[i]; d = p[E + i];
        }
        g_src[i] = s; g_dst[i] = d;
    } else if (i < E + N) {                      // self loops
        g_src[i] = i - E; g_dst[i] = i - E;
    }
}

__global__ void k_zero_deg(int N) {
    int i = blockIdx.x * blockDim.x + threadIdx.x;
    if (i < N) g_deg[i] = 0;
}

__global__ void k_hist(int Etot) {
    int i = blockIdx.x * blockDim.x + threadIdx.x;
    if (i < Etot) atomicAdd(&g_deg[g_dst[i]], 1);
}

__global__ void k_scan(int n) {                  // exclusive scan -> g_off
    __shared__ int sh[1024];
    __shared__ int carry;
    if (threadIdx.x == 0) { carry = 0; g_off[0] = 0; }
    __syncthreads();
    for (int base = 0; base < n; base += 1024) {
        int i = base + threadIdx.x;
        int v = (i < n) ? g_deg[i] : 0;
        sh[threadIdx.x] = v;
        __syncthreads();
        for (int o = 1; o < 1024; o <<= 1) {
            int t = 0;
            if (threadIdx.x >= o) t = sh[threadIdx.x - o];
            __syncthreads();
            sh[threadIdx.x] += t;
            __syncthreads();
        }
        if (i < n) g_off[i + 1] = carry + sh[threadIdx.x];
        __syncthreads();
        if (threadIdx.x == 0) carry += sh[1023];
        __syncthreads();
    }
}

__global__ void k_copy_cur(int N) {
    int i = blockIdx.x * blockDim.x + threadIdx.x;
    if (i < N) g_cur[i] = g_off[i];
}

__global__ void k_scatter(int Etot) {
    int i = blockIdx.x * blockDim.x + threadIdx.x;
    if (i < Etot) {
        int p = atomicAdd(&g_cur[g_dst[i]], 1);
        g_ssrc[p] = g_src[i];
    }
}

// ---------------- GEMM: C[M,256] = A[M,K] * B[K,256] ------------------------
// BM=128 BN=64 BK=16, 256 threads, TM=8 TN=4
__global__ __launch_bounds__(256) void k_gemm(const float* __restrict__ A,
                                              const float* __restrict__ B,
                                              float* __restrict__ C,
                                              int M, int K) {
    const int BM = 128, BN = 64, BK = 16;
    __shared__ float As[BK][BM];
    __shared__ float Bs[BK][BN];
    int tid = threadIdx.x;
    int tx = tid & 15, ty = tid >> 4;
    int brow = blockIdx.y * BM, bcol = blockIdx.x * BN;
    float acc[8][4];
    #pragma unroll
    for (int i = 0; i < 8; i++)
        #pragma unroll
        for (int j = 0; j < 4; j++) acc[i][j] = 0.f;

    for (int k0 = 0; k0 < K; k0 += BK) {
        #pragma unroll
        for (int l = 0; l < 2; l++) {
            int idx = tid + l * 256;             // 0..511 float4 ids
            int r = idx >> 2;                    // row in tile
            int kc = (idx & 3) << 2;             // k offset
            float4 v;
            if (brow + r < M) v = *(const float4*)&A[(size_t)(brow + r) * K + k0 + kc];
            else v = make_float4(0.f, 0.f, 0.f, 0.f);
            As[kc + 0][r] = v.x; As[kc + 1][r] = v.y;
            As[kc + 2][r] = v.z; As[kc + 3][r] = v.w;
        }
        {
            int r = tid >> 4;                    // 0..15
            int c = (tid & 15) << 2;             // 0..60
            *(float4*)&Bs[r][c] = *(const float4*)&B[(size_t)(k0 + r) * FDIM + bcol + c];
        }
        __syncthreads();
        #pragma unroll
        for (int k = 0; k < BK; k++) {
            float a[8], b[4];
            #pragma unroll
            for (int i = 0; i < 8; i++) a[i] = As[k][ty * 8 + i];
            #pragma unroll
            for (int j = 0; j < 4; j++) b[j] = Bs[k][tx * 4 + j];
            #pragma unroll
            for (int i = 0; i < 8; i++)
                #pragma unroll
                for (int j = 0; j < 4; j++) acc[i][j] += a[i] * b[j];
        }
        __syncthreads();
    }
    #pragma unroll
    for (int i = 0; i < 8; i++) {
        int row = brow + ty * 8 + i;
        if (row < M) {
            float4 v = make_float4(acc[i][0], acc[i][1], acc[i][2], acc[i][3]);
            *(float4*)&C[(size_t)row * FDIM + bcol + tx * 4] = v;
        }
    }
}

// GEMV for W3: h3[n] = act[n,:] . W3[:,0]
__global__ void k_dotw3(const float* __restrict__ act, const float* __restrict__ W3,
                        int N) {
    int warp = (blockIdx.x * blockDim.x + threadIdx.x) >> 5;
    int lane = threadIdx.x & 31;
    if (warp >= N) return;
    const float* row = &act[(size_t)warp * FDIM];
    float p = 0.f;
    #pragma unroll
    for (int j = 0; j < 8; j++) p += row[lane + 32 * j] * __ldg(&W3[lane + 32 * j]);
    p = wsum(p);
    if (lane == 0) g_h3[warp] = p;
}

// ---------------- attention coefficients al_src/al_dst ----------------------
__global__ void k_alphas(const float* __restrict__ h, const float* __restrict__ asrc,
                         const float* __restrict__ adst, int N) {
    int warp = (blockIdx.x * blockDim.x + threadIdx.x) >> 5;
    int lane = threadIdx.x & 31;
    if (warp >= N) return;
    const float* row = &h[(size_t)warp * FDIM];
    float ps[HEADS] = {0.f, 0.f, 0.f, 0.f};
    float pd[HEADS] = {0.f, 0.f, 0.f, 0.f};
    #pragma unroll
    for (int j = 0; j < 8; j++) {
        int c = lane + 32 * j;
        int hd = j >> 1;
        int cc = c & 63;
        float v = row[c];
        ps[hd] += v * __ldg(&asrc[hd * CH + cc]);
        pd[hd] += v * __ldg(&adst[hd * CH + cc]);
    }
    #pragma unroll
    for (int hd = 0; hd < HEADS; hd++) { ps[hd] = wsum(ps[hd]); pd[hd] = wsum(pd[hd]); }
    if (lane == 0) {
        *(float4*)&g_alsrc[warp * 4] = make_float4(ps[0], ps[1], ps[2], ps[3]);
        *(float4*)&g_aldst[warp * 4] = make_float4(pd[0], pd[1], pd[2], pd[3]);
    }
}

// ---------------- GAT aggregation (warp per dst node) -----------------------
__global__ __launch_bounds__(256) void k_aggregate(const float* __restrict__ h,
                                                   const float* __restrict__ bias,
                                                   float* __restrict__ out,
                                                   int N, int useElu) {
    int warp = (blockIdx.x * blockDim.x + threadIdx.x) >> 5;
    int lane = threadIdx.x & 31;
    if (warp >= N) return;
    int n = warp;
    int e0 = g_off[n], e1 = g_off[n + 1];
    float4 ald = *(const float4*)&g_aldst[n * 4];

    // pass 1: segment max per head
    float m0 = -1e30f, m1 = -1e30f, m2 = -1e30f, m3 = -1e30f;
    for (int e = e0 + lane; e < e1; e += 32) {
        int s = g_ssrc[e];
        float4 als = *(const float4*)&g_alsrc[s * 4];
        m0 = fmaxf(m0, lrelu(als.x + ald.x));
        m1 = fmaxf(m1, lrelu(als.y + ald.y));
        m2 = fmaxf(m2, lrelu(als.z + ald.z));
        m3 = fmaxf(m3, lrelu(als.w + ald.w));
    }
    m0 = wmax(m0); m1 = wmax(m1); m2 = wmax(m2); m3 = wmax(m3);

    // pass 2: accumulate exp-weighted messages + softmax denominators
    float acc[8] = {0.f, 0.f, 0.f, 0.f, 0.f, 0.f, 0.f, 0.f};
    float s0 = 0.f, s1 = 0.f, s2 = 0.f, s3 = 0.f;
    for (int base = e0; base < e1; base += 32) {
        int cnt = min(32, e1 - base);
        int src = 0;
        float w0 = 0.f, w1 = 0.f, w2 = 0.f, w3 = 0.f;
        if (lane < cnt) {
            src = g_ssrc[base + lane];
            float4 als = *(const float4*)&g_alsrc[src * 4];
            w0 = __expf(lrelu(als.x + ald.x) - m0);
            w1 = __expf(lrelu(als.y + ald.y) - m1);
            w2 = __expf(lrelu(als.z + ald.z) - m2);
            w3 = __expf(lrelu(als.w + ald.w) - m3);
            s0 += w0; s1 += w1; s2 += w2; s3 += w3;
        }
        for (int t = 0; t < cnt; t++) {
            int sj = __shfl_sync(0xffffffffu, src, t);
            float u0 = __shfl_sync(0xffffffffu, w0, t);
            float u1 = __shfl_sync(0xffffffffu, w1, t);
            float u2 = __shfl_sync(0xffffffffu, w2, t);
            float u3 = __shfl_sync(0xffffffffu, w3, t);
            const float* hp = &h[(size_t)sj * FDIM + lane];
            acc[0] += u0 * hp[0];   acc[1] += u0 * hp[32];
            acc[2] += u1 * hp[64];  acc[3] += u1 * hp[96];
            acc[4] += u2 * hp[128]; acc[5] += u2 * hp[160];
            acc[6] += u3 * hp[192]; acc[7] += u3 * hp[224];
        }
    }
    s0 = wsum(s0); s1 = wsum(s1); s2 = wsum(s2); s3 = wsum(s3);
    float inv[4] = {1.f / (s0 + 1e-16f), 1.f / (s1 + 1e-16f),
                    1.f / (s2 + 1e-16f), 1.f / (s3 + 1e-16f)};
    #pragma unroll
    for (int j = 0; j < 8; j++) {
        int c = lane + 32 * j;
        float v = acc[j] * inv[j >> 1] + __ldg(&bias[c]);
        if (useElu) v = v > 0.f ? v : expm1f(v);
        out[(size_t)n * FDIM + c] = v;
    }
}

// ---------------- layer 3 aggregation (scalar, thread per node) -------------
__global__ void k_agg3(const float* __restrict__ asrc3, const float* __restrict__ adst3,
                       const float* __restrict__ b3, float* __restrict__ out, int N) {
    int n = blockIdx.x * blockDim.x + threadIdx.x;
    if (n >= N) return;
    float as = __ldg(&asrc3[0]);
    float hd = g_h3[n] * __ldg(&adst3[0]);
    int e0 = g_off[n], e1 = g_off[n + 1];
    float m = -1e30f;
    for (int e = e0; e < e1; e++) {
        float l = lrelu(g_h3[g_ssrc[e]] * as + hd);
        m = fmaxf(m, l);
    }
    float num = 0.f, den = 0.f;
    for (int e = e0; e < e1; e++) {
        float hs = g_h3[g_ssrc[e]];
        float w = __expf(lrelu(hs * as + hd) - m);
        num += w * hs;
        den += w;
    }
    out[n] = num / (den + 1e-16f) + __ldg(&b3[0]);
}

// ---------------- launch ----------------------------------------------------
extern "C" void kernel_launch(void* const* d_in, const int* in_sizes, int n_in,
                              void* d_out, int out_size) {
    const float* x      = (const float*)d_in[0];
    const void*  eidx   = d_in[1];
    const float* W1     = (const float*)d_in[2];
    const float* asrc1  = (const float*)d_in[3];
    const float* adst1  = (const float*)d_in[4];
    const float* b1     = (const float*)d_in[5];
    const float* W2     = (const float*)d_in[6];
    const float* asrc2  = (const float*)d_in[7];
    const float* adst2  = (const float*)d_in[8];
    const float* b2     = (const float*)d_in[9];
    const float* W3     = (const float*)d_in[10];
    const float* asrc3  = (const float*)d_in[11];
    const float* adst3  = (const float*)d_in[12];
    const float* b3     = (const float*)d_in[13];
    float* out = (float*)d_out;

    int N = in_sizes[0] / 128;        // 50000
    int E = in_sizes[1] / 2;          // 650000
    int Etot = E + N;

    // --- build CSR by destination -------------------------------------------
    k_detect<<<1, 256>>>((const long long*)eidx, E);
    k_build_edges<<<(Etot + 255) / 256, 256>>>(eidx, E, N);
    k_zero_deg<<<(N + 255) / 256, 256>>>(N);
    k_hist<<<(Etot + 255) / 256, 256>>>(Etot);
    k_scan<<<1, 1024>>>(N);
    k_copy_cur<<<(N + 255) / 256, 256>>>(N);
    k_scatter<<<(Etot + 255) / 256, 256>>>(Etot);

    dim3 ggrid(FDIM / 64, (N + 127) / 128);
    int wblocks = (N + 7) / 8;        // warp-per-node kernels, 8 warps/block

    // --- layer 1 -------------------------------------------------------------
    k_gemm<<<ggrid, 256>>>(x, W1, g_feat, N, 128);
    k_alphas<<<wblocks, 256>>>(g_feat, asrc1, adst1, N);
    k_aggregate<<<wblocks, 256>>>(g_feat, b1, g_act, N, 1);

    // --- layer 2 -------------------------------------------------------------
    k_gemm<<<ggrid, 256>>>(g_act, W2, g_feat, N, 256);
    k_alphas<<<wblocks, 256>>>(g_feat, asrc2, adst2, N);
    k_aggregate<<<wblocks, 256>>>(g_feat, b2, g_act, N, 1);

    // --- layer 3 -------------------------------------------------------------
    k_dotw3<<<wblocks, 256>>>(g_act, W3, N);
    k_agg3<<<(N + 255) / 256, 256>>>(asrc3, adst3, b3, out, N);

    (void)n_in; (void)out_size;
}